// round 1
// baseline (speedup 1.0000x reference)
#include <cuda_runtime.h>

#define N_NODES  50000
#define N_GRAPHS 128
#define D        128

// Scratch (device globals — no allocation allowed)
__device__ float g_hw[N_NODES * D];    // H @ W result
__device__ float g_agg[N_NODES * D];   // aggregated messages (layer output)
__device__ float g_dinv[N_NODES];
__device__ int   g_deg[N_NODES];
__device__ float g_pool[N_GRAPHS * D];
__device__ float g_cnt[N_GRAPHS];

// ---------------------------------------------------------------------------
// degree / normalization
// ---------------------------------------------------------------------------
__global__ void init_deg_kernel(int n) {
    int i = blockIdx.x * blockDim.x + threadIdx.x;
    if (i < n) g_deg[i] = 1;  // self-loop
}

__global__ void count_deg_kernel(const int* __restrict__ edge_index, int E) {
    int e = blockIdx.x * blockDim.x + threadIdx.x;
    if (e < E) atomicAdd(&g_deg[edge_index[E + e]], 1);  // target (col)
}

__global__ void dinv_kernel(int n) {
    int i = blockIdx.x * blockDim.x + threadIdx.x;
    if (i < n) g_dinv[i] = rsqrtf((float)g_deg[i]);
}

// ---------------------------------------------------------------------------
// GEMM: OUT[n,128] = act(H)[n,128] @ W[128,128]
// 256 threads, 32 rows/block, 4 rows x 4 cols per thread.
// smem: W full (64KB) + H tile (16KB) = 80KB dynamic.
// ---------------------------------------------------------------------------
template <bool RELU>
__global__ void gemm_kernel(const float* __restrict__ H,
                            const float* __restrict__ W,
                            float* __restrict__ OUT, int n) {
    extern __shared__ float smem[];
    float* sW = smem;           // [128][128]
    float* sH = smem + D * D;   // [32][128]

    const int tid  = threadIdx.x;        // 0..255
    const int row0 = blockIdx.x * 32;

    // stage W (coalesced float4)
#pragma unroll
    for (int i = 0; i < 16; i++) {
        int idx = (i * 256 + tid) * 4;
        *(float4*)(sW + idx) = *(const float4*)(W + idx);
    }
    // stage H tile (32x128), optional ReLU on load
#pragma unroll
    for (int i = 0; i < 4; i++) {
        int idx = (i * 256 + tid) * 4;          // float index in tile
        int r   = row0 + (idx >> 7);            // idx / 128
        float4 v;
        if (r < n) {
            v = *(const float4*)(H + r * D + (idx & 127));
            if (RELU) {
                v.x = fmaxf(v.x, 0.f); v.y = fmaxf(v.y, 0.f);
                v.z = fmaxf(v.z, 0.f); v.w = fmaxf(v.w, 0.f);
            }
        } else {
            v = make_float4(0.f, 0.f, 0.f, 0.f);
        }
        *(float4*)(sH + idx) = v;
    }
    __syncthreads();

    const int tx = tid & 31;   // col group: cols tx*4 .. tx*4+3
    const int ty = tid >> 5;   // row group: rows ty*4 .. ty*4+3

    float4 acc0 = make_float4(0.f,0.f,0.f,0.f);
    float4 acc1 = make_float4(0.f,0.f,0.f,0.f);
    float4 acc2 = make_float4(0.f,0.f,0.f,0.f);
    float4 acc3 = make_float4(0.f,0.f,0.f,0.f);

#pragma unroll 4
    for (int k = 0; k < D; k++) {
        float4 w = *(float4*)(sW + k * D + tx * 4);
        float h0 = sH[(ty * 4 + 0) * D + k];
        float h1 = sH[(ty * 4 + 1) * D + k];
        float h2 = sH[(ty * 4 + 2) * D + k];
        float h3 = sH[(ty * 4 + 3) * D + k];
        acc0.x += h0 * w.x; acc0.y += h0 * w.y; acc0.z += h0 * w.z; acc0.w += h0 * w.w;
        acc1.x += h1 * w.x; acc1.y += h1 * w.y; acc1.z += h1 * w.z; acc1.w += h1 * w.w;
        acc2.x += h2 * w.x; acc2.y += h2 * w.y; acc2.z += h2 * w.z; acc2.w += h2 * w.w;
        acc3.x += h3 * w.x; acc3.y += h3 * w.y; acc3.z += h3 * w.z; acc3.w += h3 * w.w;
    }

    const int col = tx * 4;
    int r = row0 + ty * 4;
    if (r + 0 < n) *(float4*)(OUT + (r + 0) * D + col) = acc0;
    if (r + 1 < n) *(float4*)(OUT + (r + 1) * D + col) = acc1;
    if (r + 2 < n) *(float4*)(OUT + (r + 2) * D + col) = acc2;
    if (r + 3 < n) *(float4*)(OUT + (r + 3) * D + col) = acc3;
}

// ---------------------------------------------------------------------------
// agg[i] = hw[i] * dinv[i]^2 + b     (self-loop + bias, also clears buffer)
// ---------------------------------------------------------------------------
__global__ void init_agg_kernel(const float* __restrict__ b, int n) {
    int i = blockIdx.x;
    int c = threadIdx.x;
    if (i >= n) return;
    float s = g_dinv[i];
    g_agg[i * D + c] = g_hw[i * D + c] * (s * s) + b[c];
}

// ---------------------------------------------------------------------------
// scatter: agg[col] += hw[row] * dinv[row]*dinv[col]   (one warp per edge)
// ---------------------------------------------------------------------------
__global__ void scatter_kernel(const int* __restrict__ edge_index, int E) {
    int e    = blockIdx.x * 8 + (threadIdx.x >> 5);
    int lane = threadIdx.x & 31;
    if (e >= E) return;
    int row = edge_index[e];
    int col = edge_index[E + e];
    float norm = g_dinv[row] * g_dinv[col];
    const float* src = g_hw + row * D;
    float* dst = g_agg + col * D;
#pragma unroll
    for (int j = 0; j < 4; j++) {
        int c = lane + 32 * j;
        atomicAdd(dst + c, __ldg(src + c) * norm);
    }
}

// ---------------------------------------------------------------------------
// pooling
// ---------------------------------------------------------------------------
__global__ void zero_pool_kernel() {
    int i = blockIdx.x * blockDim.x + threadIdx.x;
    if (i < N_GRAPHS * D) g_pool[i] = 0.f;
    if (i < N_GRAPHS) g_cnt[i] = 0.f;
}

__global__ void pool_kernel(const int* __restrict__ batch, int n) {
    int i = blockIdx.x;
    int c = threadIdx.x;
    if (i >= n) return;
    int b = batch[i];
    atomicAdd(&g_pool[b * D + c], g_agg[i * D + c]);
    if (c == 0) atomicAdd(&g_cnt[b], 1.f);
}

__global__ void head_kernel(const float* __restrict__ Wlin,
                            const float* __restrict__ blin,
                            float* __restrict__ out) {
    int g = threadIdx.x;  // 128 graphs
    float cnt = fmaxf(g_cnt[g], 1.f);
    float inv = 1.f / cnt;
    float a0 = blin[0], a1 = blin[1], a2 = blin[2];
#pragma unroll 4
    for (int k = 0; k < D; k++) {
        float p = g_pool[g * D + k] * inv;
        a0 += p * Wlin[k * 3 + 0];
        a1 += p * Wlin[k * 3 + 1];
        a2 += p * Wlin[k * 3 + 2];
    }
    out[g * 3 + 0] = a0;
    out[g * 3 + 1] = a1;
    out[g * 3 + 2] = a2;
}

// ---------------------------------------------------------------------------
// launch
// ---------------------------------------------------------------------------
extern "C" void kernel_launch(void* const* d_in, const int* in_sizes, int n_in,
                              void* d_out, int out_size) {
    const float* x     = (const float*)d_in[0];
    const int*   ei    = (const int*)  d_in[1];
    const int*   batch = (const int*)  d_in[2];
    const float* W1    = (const float*)d_in[3];
    const float* b1    = (const float*)d_in[4];
    const float* W2    = (const float*)d_in[5];
    const float* b2    = (const float*)d_in[6];
    const float* W3    = (const float*)d_in[7];
    const float* b3    = (const float*)d_in[8];
    const float* Wlin  = (const float*)d_in[9];
    const float* blin  = (const float*)d_in[10];
    float* out = (float*)d_out;

    const int n = in_sizes[0] / D;       // 50000
    const int E = in_sizes[1] / 2;       // 800000

    float* hw_ptr;
    cudaGetSymbolAddress((void**)&hw_ptr, g_hw);
    float* agg_ptr;
    cudaGetSymbolAddress((void**)&agg_ptr, g_agg);

    const int SMEM = (D * D + 32 * D) * (int)sizeof(float);  // 80KB
    cudaFuncSetAttribute(gemm_kernel<false>,
                         cudaFuncAttributeMaxDynamicSharedMemorySize, SMEM);
    cudaFuncSetAttribute(gemm_kernel<true>,
                         cudaFuncAttributeMaxDynamicSharedMemorySize, SMEM);

    const int gemm_blocks = (n + 31) / 32;
    const int scat_blocks = (E + 7) / 8;

    // normalization
    init_deg_kernel<<<(n + 255) / 256, 256>>>(n);
    count_deg_kernel<<<(E + 255) / 256, 256>>>(ei, E);
    dinv_kernel<<<(n + 255) / 256, 256>>>(n);

    // layer 1
    gemm_kernel<false><<<gemm_blocks, 256, SMEM>>>(x, W1, hw_ptr, n);
    init_agg_kernel<<<n, D>>>(b1, n);
    scatter_kernel<<<scat_blocks, 256>>>(ei, E);

    // layer 2 (relu on read of agg)
    gemm_kernel<true><<<gemm_blocks, 256, SMEM>>>(agg_ptr, W2, hw_ptr, n);
    init_agg_kernel<<<n, D>>>(b2, n);
    scatter_kernel<<<scat_blocks, 256>>>(ei, E);

    // layer 3 (relu on read of agg)
    gemm_kernel<true><<<gemm_blocks, 256, SMEM>>>(agg_ptr, W3, hw_ptr, n);
    init_agg_kernel<<<n, D>>>(b3, n);
    scatter_kernel<<<scat_blocks, 256>>>(ei, E);

    // mean pool + head
    zero_pool_kernel<<<(N_GRAPHS * D + 255) / 256, 256>>>();
    pool_kernel<<<n, D>>>(batch, n);
    head_kernel<<<1, N_GRAPHS>>>(Wlin, blin, out);
}

// round 3
// speedup vs baseline: 1.2396x; 1.2396x over previous
#include <cuda_runtime.h>

#define N_NODES  50000
#define N_EDGES  800000
#define N_GRAPHS 128
#define D        128

// Scratch (device globals — no allocation allowed)
__device__ float g_hw[N_NODES * D];     // H @ W result
__device__ float g_agg[N_NODES * D];    // aggregated layer output
__device__ float g_dinv[N_NODES];
__device__ int   g_ecnt[N_NODES];       // in-edge count (excl. self-loop)
__device__ int   g_off[N_NODES];        // CSR offsets
__device__ int   g_cur[N_NODES];        // fill cursors
__device__ int2  g_pay[N_EDGES];        // (src, norm_bits) sorted by dst

// ---------------------------------------------------------------------------
// CSR build: histogram -> scan (+dinv) -> fill
// ---------------------------------------------------------------------------
__global__ void zero_cnt_kernel(int n) {
    int i = blockIdx.x * blockDim.x + threadIdx.x;
    if (i < n) g_ecnt[i] = 0;
}

__global__ void hist_kernel(const int* __restrict__ ei, int E) {
    int e = blockIdx.x * blockDim.x + threadIdx.x;
    if (e < E) atomicAdd(&g_ecnt[ei[E + e]], 1);
}

// single block, 1024 threads: exclusive scan over 50000 counts
__global__ void scan_kernel(int n) {
    __shared__ int part[1024];
    const int t = threadIdx.x;
    const int chunk = (n + 1023) / 1024;
    const int s = t * chunk;
    const int e = min(s + chunk, n);
    int sum = 0;
    for (int i = s; i < e; i++) sum += g_ecnt[i];
    part[t] = sum;
    __syncthreads();
    for (int d = 1; d < 1024; d <<= 1) {
        int v = (t >= d) ? part[t - d] : 0;
        __syncthreads();
        part[t] += v;
        __syncthreads();
    }
    int run = part[t] - sum;   // exclusive prefix
    for (int i = s; i < e; i++) {
        int c = g_ecnt[i];
        g_off[i] = run;
        g_cur[i] = run;
        g_dinv[i] = rsqrtf((float)(c + 1));   // +1 self-loop
        run += c;
    }
}

__global__ void fill_kernel(const int* __restrict__ ei, int E) {
    int e = blockIdx.x * blockDim.x + threadIdx.x;
    if (e >= E) return;
    int row = ei[e];
    int col = ei[E + e];
    int pos = atomicAdd(&g_cur[col], 1);
    float norm = g_dinv[row] * g_dinv[col];
    g_pay[pos] = make_int2(row, __float_as_int(norm));
}

// ---------------------------------------------------------------------------
// fma helper (NO macro: avoids token collision with float4 members)
// ---------------------------------------------------------------------------
__device__ __forceinline__ void fma4(float4& acc, float h, const float4& v) {
    acc.x = fmaf(h, v.x, acc.x);
    acc.y = fmaf(h, v.y, acc.y);
    acc.z = fmaf(h, v.z, acc.z);
    acc.w = fmaf(h, v.w, acc.w);
}

// ---------------------------------------------------------------------------
// GEMM: OUT[n,128] = act(H)[n,128] @ W[128,128]
// 256 threads, 32 rows/block, 4x4 outputs/thread, k vectorized by 4.
// W staged in two 64-k chunks -> 48KB static smem -> 4 blocks/SM.
// ---------------------------------------------------------------------------
template <bool RELU>
__global__ __launch_bounds__(256) void gemm_kernel(const float* __restrict__ H,
                                                   const float* __restrict__ W,
                                                   float* __restrict__ OUT, int n) {
    __shared__ float sW[64 * D];   // 32KB (one k-chunk)
    __shared__ float sH[32 * D];   // 16KB

    const int tid  = threadIdx.x;
    const int row0 = blockIdx.x * 32;

    // stage H tile (32x128) with optional ReLU
#pragma unroll
    for (int i = 0; i < 4; i++) {
        int idx = (i * 256 + tid) * 4;
        int r   = row0 + (idx >> 7);
        float4 v;
        if (r < n) {
            v = *(const float4*)(H + r * D + (idx & 127));
            if (RELU) {
                v.x = fmaxf(v.x, 0.f); v.y = fmaxf(v.y, 0.f);
                v.z = fmaxf(v.z, 0.f); v.w = fmaxf(v.w, 0.f);
            }
        } else {
            v = make_float4(0.f, 0.f, 0.f, 0.f);
        }
        *(float4*)(sH + idx) = v;
    }

    const int tx = tid & 31;    // cols tx*4 .. tx*4+3
    const int ty = tid >> 5;    // rows ty*4 .. ty*4+3

    float4 acc0 = make_float4(0.f,0.f,0.f,0.f);
    float4 acc1 = make_float4(0.f,0.f,0.f,0.f);
    float4 acc2 = make_float4(0.f,0.f,0.f,0.f);
    float4 acc3 = make_float4(0.f,0.f,0.f,0.f);

#pragma unroll
    for (int kc = 0; kc < 2; kc++) {
        __syncthreads();   // covers H stage (kc=0) / prior chunk compute (kc=1)
        // stage W rows [kc*64, kc*64+64)
#pragma unroll
        for (int i = 0; i < 8; i++) {
            int idx = (i * 256 + tid) * 4;
            *(float4*)(sW + idx) = *(const float4*)(W + kc * 64 * D + idx);
        }
        __syncthreads();

#pragma unroll 2
        for (int k = 0; k < 64; k += 4) {
            float4 w0 = *(float4*)(sW + (k + 0) * D + tx * 4);
            float4 w1 = *(float4*)(sW + (k + 1) * D + tx * 4);
            float4 w2 = *(float4*)(sW + (k + 2) * D + tx * 4);
            float4 w3 = *(float4*)(sW + (k + 3) * D + tx * 4);
            int hk = kc * 64 + k;
            float4 h0 = *(float4*)(sH + (ty * 4 + 0) * D + hk);
            float4 h1 = *(float4*)(sH + (ty * 4 + 1) * D + hk);
            float4 h2 = *(float4*)(sH + (ty * 4 + 2) * D + hk);
            float4 h3 = *(float4*)(sH + (ty * 4 + 3) * D + hk);

            fma4(acc0, h0.x, w0); fma4(acc0, h0.y, w1); fma4(acc0, h0.z, w2); fma4(acc0, h0.w, w3);
            fma4(acc1, h1.x, w0); fma4(acc1, h1.y, w1); fma4(acc1, h1.z, w2); fma4(acc1, h1.w, w3);
            fma4(acc2, h2.x, w0); fma4(acc2, h2.y, w1); fma4(acc2, h2.z, w2); fma4(acc2, h2.w, w3);
            fma4(acc3, h3.x, w0); fma4(acc3, h3.y, w1); fma4(acc3, h3.z, w2); fma4(acc3, h3.w, w3);
        }
    }

    const int col = tx * 4;
    int r = row0 + ty * 4;
    if (r + 0 < n) *(float4*)(OUT + (r + 0) * D + col) = acc0;
    if (r + 1 < n) *(float4*)(OUT + (r + 1) * D + col) = acc1;
    if (r + 2 < n) *(float4*)(OUT + (r + 2) * D + col) = acc2;
    if (r + 3 < n) *(float4*)(OUT + (r + 3) * D + col) = acc3;
}

// ---------------------------------------------------------------------------
// Gather aggregation: agg[i] = hw[i]*dinv[i]^2 + b + sum_in hw[src]*norm
// One block (128 threads) per node; no atomics; MLP=4 prefetch.
// ---------------------------------------------------------------------------
__global__ __launch_bounds__(128) void gather_kernel(const float* __restrict__ b, int n) {
    const int i = blockIdx.x;
    if (i >= n) return;
    const int c = threadIdx.x;

    float s = g_dinv[i];
    float acc = fmaf(g_hw[i * D + c], s * s, b[c]);

    const int off = g_off[i];
    const int deg = g_ecnt[i];
    const int2* __restrict__ pay = g_pay + off;

    int j = 0;
    for (; j + 4 <= deg; j += 4) {
        int2 p0 = pay[j + 0];
        int2 p1 = pay[j + 1];
        int2 p2 = pay[j + 2];
        int2 p3 = pay[j + 3];
        float v0 = __ldg(g_hw + p0.x * D + c);
        float v1 = __ldg(g_hw + p1.x * D + c);
        float v2 = __ldg(g_hw + p2.x * D + c);
        float v3 = __ldg(g_hw + p3.x * D + c);
        acc = fmaf(v0, __int_as_float(p0.y), acc);
        acc = fmaf(v1, __int_as_float(p1.y), acc);
        acc = fmaf(v2, __int_as_float(p2.y), acc);
        acc = fmaf(v3, __int_as_float(p3.y), acc);
    }
    for (; j < deg; j++) {
        int2 p = pay[j];
        acc = fmaf(__ldg(g_hw + p.x * D + c), __int_as_float(p.y), acc);
    }
    g_agg[i * D + c] = acc;
}

// ---------------------------------------------------------------------------
// Fused mean-pool (sorted batch, binary search) + 128->3 head.
// 128 blocks (one per graph), 128 threads.
// ---------------------------------------------------------------------------
__global__ __launch_bounds__(128) void pool_head_kernel(const int* __restrict__ batch,
                                                        const float* __restrict__ Wlin,
                                                        const float* __restrict__ blin,
                                                        float* __restrict__ out, int n) {
    __shared__ float sp[D];
    __shared__ int bounds[2];
    const int g = blockIdx.x;
    const int c = threadIdx.x;

    if (c < 2) {
        int target = g + c;   // c==0: start (first >= g), c==1: end (first >= g+1)
        int lo = 0, hi = n;
        while (lo < hi) {
            int m = (lo + hi) >> 1;
            if (batch[m] < target) lo = m + 1; else hi = m;
        }
        bounds[c] = lo;
    }
    __syncthreads();
    const int start = bounds[0], end = bounds[1];

    float acc = 0.f;
    for (int i = start; i < end; i++)
        acc += g_agg[i * D + c];
    float cnt = fmaxf((float)(end - start), 1.f);
    sp[c] = acc / cnt;
    __syncthreads();

    if (c < 3) {
        float a = blin[c];
#pragma unroll 8
        for (int k = 0; k < D; k++)
            a = fmaf(sp[k], Wlin[k * 3 + c], a);
        out[g * 3 + c] = a;
    }
}

// ---------------------------------------------------------------------------
// launch
// ---------------------------------------------------------------------------
extern "C" void kernel_launch(void* const* d_in, const int* in_sizes, int n_in,
                              void* d_out, int out_size) {
    const float* x     = (const float*)d_in[0];
    const int*   ei    = (const int*)  d_in[1];
    const int*   batch = (const int*)  d_in[2];
    const float* W1    = (const float*)d_in[3];
    const float* b1    = (const float*)d_in[4];
    const float* W2    = (const float*)d_in[5];
    const float* b2    = (const float*)d_in[6];
    const float* W3    = (const float*)d_in[7];
    const float* b3    = (const float*)d_in[8];
    const float* Wlin  = (const float*)d_in[9];
    const float* blin  = (const float*)d_in[10];
    float* out = (float*)d_out;

    const int n = in_sizes[0] / D;   // 50000
    const int E = in_sizes[1] / 2;   // 800000

    float* hw_ptr;
    cudaGetSymbolAddress((void**)&hw_ptr, g_hw);
    float* agg_ptr;
    cudaGetSymbolAddress((void**)&agg_ptr, g_agg);

    const int gemm_blocks = (n + 31) / 32;

    // CSR build + normalization
    zero_cnt_kernel<<<(n + 255) / 256, 256>>>(n);
    hist_kernel<<<(E + 255) / 256, 256>>>(ei, E);
    scan_kernel<<<1, 1024>>>(n);
    fill_kernel<<<(E + 255) / 256, 256>>>(ei, E);

    // layer 1
    gemm_kernel<false><<<gemm_blocks, 256>>>(x, W1, hw_ptr, n);
    gather_kernel<<<n, D>>>(b1, n);

    // layer 2 (relu fused into GEMM load)
    gemm_kernel<true><<<gemm_blocks, 256>>>(agg_ptr, W2, hw_ptr, n);
    gather_kernel<<<n, D>>>(b2, n);

    // layer 3
    gemm_kernel<true><<<gemm_blocks, 256>>>(agg_ptr, W3, hw_ptr, n);
    gather_kernel<<<n, D>>>(b3, n);

    // fused mean pool + head
    pool_head_kernel<<<N_GRAPHS, D>>>(batch, Wlin, blin, out, n);
}

// round 4
// speedup vs baseline: 1.3054x; 1.0531x over previous
#include <cuda_runtime.h>

#define N_NODES  50000
#define N_EDGES  800000
#define N_GRAPHS 128
#define D        128

// Scratch (device globals — no allocation allowed)
__device__ float g_hw[N_NODES * D];     // (H @ W) * dinv[row]
__device__ float g_agg[N_NODES * D];    // aggregated layer output
__device__ float g_dinv[N_NODES];
__device__ int   g_ecnt[N_NODES];       // in-edge count (excl. self-loop)
__device__ int   g_off[N_NODES];        // CSR offsets
__device__ int   g_cur[N_NODES];        // fill cursors
__device__ int   g_srcs[N_EDGES];       // src node ids, grouped by dst

// ---------------------------------------------------------------------------
// CSR build: histogram -> scan (+dinv) -> fill
// ---------------------------------------------------------------------------
__global__ void zero_cnt_kernel(int n) {
    int i = blockIdx.x * blockDim.x + threadIdx.x;
    if (i < n) g_ecnt[i] = 0;
}

__global__ void hist_kernel(const int* __restrict__ ei, int E) {
    int e = blockIdx.x * blockDim.x + threadIdx.x;
    if (e < E) atomicAdd(&g_ecnt[ei[E + e]], 1);
}

// single block, 1024 threads: exclusive scan over 50000 counts
__global__ void scan_kernel(int n) {
    __shared__ int part[1024];
    const int t = threadIdx.x;
    const int chunk = (n + 1023) / 1024;
    const int s = t * chunk;
    const int e = min(s + chunk, n);
    int sum = 0;
    for (int i = s; i < e; i++) sum += g_ecnt[i];
    part[t] = sum;
    __syncthreads();
    for (int d = 1; d < 1024; d <<= 1) {
        int v = (t >= d) ? part[t - d] : 0;
        __syncthreads();
        part[t] += v;
        __syncthreads();
    }
    int run = part[t] - sum;   // exclusive prefix
    for (int i = s; i < e; i++) {
        int c = g_ecnt[i];
        g_off[i] = run;
        g_cur[i] = run;
        g_dinv[i] = rsqrtf((float)(c + 1));   // +1 self-loop
        run += c;
    }
}

__global__ void fill_kernel(const int* __restrict__ ei, int E) {
    int e = blockIdx.x * blockDim.x + threadIdx.x;
    if (e >= E) return;
    int row = ei[e];
    int col = ei[E + e];
    int pos = atomicAdd(&g_cur[col], 1);
    g_srcs[pos] = row;
}

// ---------------------------------------------------------------------------
// packed f32x2 helpers
// ---------------------------------------------------------------------------
__device__ __forceinline__ unsigned long long bcast2(float v) {
    unsigned long long r;
    asm("mov.b64 %0, {%1, %1};" : "=l"(r) : "r"(__float_as_uint(v)));
    return r;
}
__device__ __forceinline__ void fma2(unsigned long long& acc,
                                     unsigned long long a,
                                     unsigned long long b) {
    asm("fma.rn.f32x2 %0, %1, %2, %0;" : "+l"(acc) : "l"(a), "l"(b));
}
__device__ __forceinline__ void mul2(unsigned long long& d,
                                     unsigned long long s) {
    asm("mul.rn.f32x2 %0, %0, %1;" : "+l"(d) : "l"(s));
}

// ---------------------------------------------------------------------------
// GEMM: OUT[r,:] = (act(H)[r,:] @ W) * dinv[r]
// 256 threads, 64 rows/block, 4 rows x 8 cols per thread, fma.rn.f32x2.
// dynamic smem: W full 64KB + H tile 32KB = 96KB -> 2 blocks/SM.
// ---------------------------------------------------------------------------
template <bool RELU>
__global__ __launch_bounds__(256, 2) void gemm_kernel(const float* __restrict__ H,
                                                      const float* __restrict__ W,
                                                      float* __restrict__ OUT, int n) {
    extern __shared__ float smem[];
    float* sW = smem;            // [128][128] 64KB
    float* sH = smem + D * D;    // [64][128]  32KB

    const int tid  = threadIdx.x;
    const int row0 = blockIdx.x * 64;

    // stage W (full, coalesced float4)
#pragma unroll
    for (int i = 0; i < 16; i++) {
        int idx = (i * 256 + tid) * 4;
        *(float4*)(sW + idx) = *(const float4*)(W + idx);
    }
    // stage H tile (64x128) with optional ReLU
#pragma unroll
    for (int i = 0; i < 8; i++) {
        int idx = (i * 256 + tid) * 4;
        int r   = row0 + (idx >> 7);
        float4 v;
        if (r < n) {
            v = *(const float4*)(H + r * D + (idx & 127));
            if (RELU) {
                v.x = fmaxf(v.x, 0.f); v.y = fmaxf(v.y, 0.f);
                v.z = fmaxf(v.z, 0.f); v.w = fmaxf(v.w, 0.f);
            }
        } else {
            v = make_float4(0.f, 0.f, 0.f, 0.f);
        }
        *(float4*)(sH + idx) = v;
    }
    __syncthreads();

    const int tx = tid & 15;    // col group: 8 cols at tx*8
    const int ty = tid >> 4;    // rows ty*4 .. ty*4+3

    unsigned long long acc[4][4] = {};   // [row][pair], pair p = cols 2p,2p+1

#pragma unroll 2
    for (int k = 0; k < D; k += 4) {
        float4 h0 = *(float4*)(sH + (ty * 4 + 0) * D + k);
        float4 h1 = *(float4*)(sH + (ty * 4 + 1) * D + k);
        float4 h2 = *(float4*)(sH + (ty * 4 + 2) * D + k);
        float4 h3 = *(float4*)(sH + (ty * 4 + 3) * D + k);
#pragma unroll
        for (int kk = 0; kk < 4; kk++) {
            const ulonglong2* wr = (const ulonglong2*)(sW + (k + kk) * D + tx * 8);
            ulonglong2 wa = wr[0];   // cols 0..3 (pairs 0,1)
            ulonglong2 wb = wr[1];   // cols 4..7 (pairs 2,3)
            float hv0 = (kk == 0) ? h0.x : (kk == 1) ? h0.y : (kk == 2) ? h0.z : h0.w;
            float hv1 = (kk == 0) ? h1.x : (kk == 1) ? h1.y : (kk == 2) ? h1.z : h1.w;
            float hv2 = (kk == 0) ? h2.x : (kk == 1) ? h2.y : (kk == 2) ? h2.z : h2.w;
            float hv3 = (kk == 0) ? h3.x : (kk == 1) ? h3.y : (kk == 2) ? h3.z : h3.w;
            unsigned long long p0 = bcast2(hv0);
            unsigned long long p1 = bcast2(hv1);
            unsigned long long p2 = bcast2(hv2);
            unsigned long long p3 = bcast2(hv3);
            fma2(acc[0][0], p0, wa.x); fma2(acc[0][1], p0, wa.y);
            fma2(acc[0][2], p0, wb.x); fma2(acc[0][3], p0, wb.y);
            fma2(acc[1][0], p1, wa.x); fma2(acc[1][1], p1, wa.y);
            fma2(acc[1][2], p1, wb.x); fma2(acc[1][3], p1, wb.y);
            fma2(acc[2][0], p2, wa.x); fma2(acc[2][1], p2, wa.y);
            fma2(acc[2][2], p2, wb.x); fma2(acc[2][3], p2, wb.y);
            fma2(acc[3][0], p3, wa.x); fma2(acc[3][1], p3, wa.y);
            fma2(acc[3][2], p3, wb.x); fma2(acc[3][3], p3, wb.y);
        }
    }

    const int col = tx * 8;
#pragma unroll
    for (int i = 0; i < 4; i++) {
        int r = row0 + ty * 4 + i;
        if (r < n) {
            unsigned long long sp = bcast2(g_dinv[r]);
            mul2(acc[i][0], sp); mul2(acc[i][1], sp);
            mul2(acc[i][2], sp); mul2(acc[i][3], sp);
            ulonglong2* o = (ulonglong2*)(OUT + r * D + col);
            o[0] = make_ulonglong2(acc[i][0], acc[i][1]);
            o[1] = make_ulonglong2(acc[i][2], acc[i][3]);
        }
    }
}

// ---------------------------------------------------------------------------
// Gather aggregation (warp per node, float4 per lane):
// agg[i] = dinv[i] * (hw'[i] + sum_in hw'[src]) + b
// ---------------------------------------------------------------------------
__global__ __launch_bounds__(256) void gather_kernel(const float* __restrict__ b, int n) {
    const int node = blockIdx.x * 8 + (threadIdx.x >> 5);
    const int lane = threadIdx.x & 31;
    if (node >= n) return;

    const float4* __restrict__ hw4 = (const float4*)g_hw;
    float4 acc = hw4[node * 32 + lane];   // self term (hw' includes dinv[src])

    const int off = g_off[node];
    const int deg = g_ecnt[node];
    const int* __restrict__ src = g_srcs + off;

    int j = 0;
    for (; j + 4 <= deg; j += 4) {
        int s0 = src[j + 0], s1 = src[j + 1], s2 = src[j + 2], s3 = src[j + 3];
        float4 v0 = __ldg(hw4 + s0 * 32 + lane);
        float4 v1 = __ldg(hw4 + s1 * 32 + lane);
        float4 v2 = __ldg(hw4 + s2 * 32 + lane);
        float4 v3 = __ldg(hw4 + s3 * 32 + lane);
        acc.x += v0.x + v1.x + v2.x + v3.x;
        acc.y += v0.y + v1.y + v2.y + v3.y;
        acc.z += v0.z + v1.z + v2.z + v3.z;
        acc.w += v0.w + v1.w + v2.w + v3.w;
    }
    for (; j < deg; j++) {
        float4 v = __ldg(hw4 + src[j] * 32 + lane);
        acc.x += v.x; acc.y += v.y; acc.z += v.z; acc.w += v.w;
    }

    float s = g_dinv[node];
    float4 bb = ((const float4*)b)[lane];
    float4 out;
    out.x = fmaf(acc.x, s, bb.x);
    out.y = fmaf(acc.y, s, bb.y);
    out.z = fmaf(acc.z, s, bb.z);
    out.w = fmaf(acc.w, s, bb.w);
    ((float4*)g_agg)[node * 32 + lane] = out;
}

// ---------------------------------------------------------------------------
// Fused mean-pool (sorted batch, binary search) + 128->3 head.
// ---------------------------------------------------------------------------
__global__ __launch_bounds__(128) void pool_head_kernel(const int* __restrict__ batch,
                                                        const float* __restrict__ Wlin,
                                                        const float* __restrict__ blin,
                                                        float* __restrict__ out, int n) {
    __shared__ float sp[D];
    __shared__ int bounds[2];
    const int g = blockIdx.x;
    const int c = threadIdx.x;

    if (c < 2) {
        int target = g + c;
        int lo = 0, hi = n;
        while (lo < hi) {
            int m = (lo + hi) >> 1;
            if (batch[m] < target) lo = m + 1; else hi = m;
        }
        bounds[c] = lo;
    }
    __syncthreads();
    const int start = bounds[0], end = bounds[1];

    float acc = 0.f;
    for (int i = start; i < end; i++)
        acc += g_agg[i * D + c];
    float cnt = fmaxf((float)(end - start), 1.f);
    sp[c] = acc / cnt;
    __syncthreads();

    if (c < 3) {
        float a = blin[c];
#pragma unroll 8
        for (int k = 0; k < D; k++)
            a = fmaf(sp[k], Wlin[k * 3 + c], a);
        out[g * 3 + c] = a;
    }
}

// ---------------------------------------------------------------------------
// launch
// ---------------------------------------------------------------------------
extern "C" void kernel_launch(void* const* d_in, const int* in_sizes, int n_in,
                              void* d_out, int out_size) {
    const float* x     = (const float*)d_in[0];
    const int*   ei    = (const int*)  d_in[1];
    const int*   batch = (const int*)  d_in[2];
    const float* W1    = (const float*)d_in[3];
    const float* b1    = (const float*)d_in[4];
    const float* W2    = (const float*)d_in[5];
    const float* b2    = (const float*)d_in[6];
    const float* W3    = (const float*)d_in[7];
    const float* b3    = (const float*)d_in[8];
    const float* Wlin  = (const float*)d_in[9];
    const float* blin  = (const float*)d_in[10];
    float* out = (float*)d_out;

    const int n = in_sizes[0] / D;   // 50000
    const int E = in_sizes[1] / 2;   // 800000

    float* hw_ptr;
    cudaGetSymbolAddress((void**)&hw_ptr, g_hw);
    float* agg_ptr;
    cudaGetSymbolAddress((void**)&agg_ptr, g_agg);

    const int SMEM = (D * D + 64 * D) * (int)sizeof(float);  // 96KB
    cudaFuncSetAttribute(gemm_kernel<false>,
                         cudaFuncAttributeMaxDynamicSharedMemorySize, SMEM);
    cudaFuncSetAttribute(gemm_kernel<true>,
                         cudaFuncAttributeMaxDynamicSharedMemorySize, SMEM);

    const int gemm_blocks = (n + 63) / 64;
    const int gath_blocks = (n + 7) / 8;

    // CSR build + normalization
    zero_cnt_kernel<<<(n + 255) / 256, 256>>>(n);
    hist_kernel<<<(E + 255) / 256, 256>>>(ei, E);
    scan_kernel<<<1, 1024>>>(n);
    fill_kernel<<<(E + 255) / 256, 256>>>(ei, E);

    // layer 1
    gemm_kernel<false><<<gemm_blocks, 256, SMEM>>>(x, W1, hw_ptr, n);
    gather_kernel<<<gath_blocks, 256>>>(b1, n);

    // layer 2 (relu fused into GEMM load)
    gemm_kernel<true><<<gemm_blocks, 256, SMEM>>>(agg_ptr, W2, hw_ptr, n);
    gather_kernel<<<gath_blocks, 256>>>(b2, n);

    // layer 3
    gemm_kernel<true><<<gemm_blocks, 256, SMEM>>>(agg_ptr, W3, hw_ptr, n);
    gather_kernel<<<gath_blocks, 256>>>(b3, n);

    // fused mean pool + head
    pool_head_kernel<<<N_GRAPHS, D>>>(batch, Wlin, blin, out, n);
}